// round 1
// baseline (speedup 1.0000x reference)
#include <cuda_runtime.h>
#include <math.h>

// Problem constants
#define BATCH 4
#define T 4096
#define D 512
#define CHK 128                 // query chunk
#define NQC (T / CHK)           // 32 query chunks
#define WKEYS 512               // banded window: 4 key chunks of 128
#define MTOT (BATCH * T)        // 16384 rows

// Scratch (static device arrays; no allocation in kernel_launch)
__device__ float g_q[BATCH * T * D];
__device__ float g_k[BATCH * T * D];
__device__ float g_v[BATCH * T * D];
__device__ float g_ws[BATCH * NQC * CHK * WKEYS];
__device__ float g_r[BATCH * T * D];

// ---------------------------------------------------------------------------
// Shared SGEMM tile pattern: BM=BN=128, BK=8, 256 threads, 8x8 per thread.
// Rows/cols per thread are split as {ty*4+i, 64+ty*4+i} to get float4 smem reads.
// ---------------------------------------------------------------------------

// NT GEMM: C[r,c] = sum_k A[r,k] * B[c,k]   (both row-major, K-contiguous)
// Used for QKV projection, scores (with weight epilogue), output projection.

__global__ __launch_bounds__(256) void qkv_gemm(
    const float* __restrict__ x,
    const float* __restrict__ Wq,
    const float* __restrict__ Wk,
    const float* __restrict__ Wv)
{
    const float* W = (blockIdx.z == 0) ? Wq : (blockIdx.z == 1) ? Wk : Wv;
    float* C = (blockIdx.z == 0) ? g_q : (blockIdx.z == 1) ? g_k : g_v;

    const int row0 = blockIdx.y * 128;   // M = 16384
    const int col0 = blockIdx.x * 128;   // N = 512

    __shared__ float As[8][128];
    __shared__ float Bs[8][128];
    float acc[8][8];
#pragma unroll
    for (int i = 0; i < 8; i++)
#pragma unroll
        for (int j = 0; j < 8; j++) acc[i][j] = 0.f;

    const int tid = threadIdx.x;
    const int tx = tid & 15, ty = tid >> 4;
    const int ldrow = tid >> 1;
    const int ldk = (tid & 1) * 4;

    const float* A = x + (size_t)row0 * D;
    const float* Bm = W + (size_t)col0 * D;

    for (int k0 = 0; k0 < D; k0 += 8) {
        float4 a4 = *(const float4*)(A + (size_t)ldrow * D + k0 + ldk);
        As[ldk + 0][ldrow] = a4.x; As[ldk + 1][ldrow] = a4.y;
        As[ldk + 2][ldrow] = a4.z; As[ldk + 3][ldrow] = a4.w;
        float4 b4 = *(const float4*)(Bm + (size_t)ldrow * D + k0 + ldk);
        Bs[ldk + 0][ldrow] = b4.x; Bs[ldk + 1][ldrow] = b4.y;
        Bs[ldk + 2][ldrow] = b4.z; Bs[ldk + 3][ldrow] = b4.w;
        __syncthreads();
#pragma unroll
        for (int kk = 0; kk < 8; kk++) {
            float ar[8], br[8];
            *(float4*)&ar[0] = *(const float4*)&As[kk][ty * 4];
            *(float4*)&ar[4] = *(const float4*)&As[kk][64 + ty * 4];
            *(float4*)&br[0] = *(const float4*)&Bs[kk][tx * 4];
            *(float4*)&br[4] = *(const float4*)&Bs[kk][64 + tx * 4];
#pragma unroll
            for (int i = 0; i < 8; i++)
#pragma unroll
                for (int j = 0; j < 8; j++) acc[i][j] += ar[i] * br[j];
        }
        __syncthreads();
    }

#pragma unroll
    for (int i = 0; i < 8; i++) {
        int r = (i < 4) ? (ty * 4 + i) : (64 + ty * 4 + i - 4);
#pragma unroll
        for (int j = 0; j < 8; j++) {
            int c = (j < 4) ? (tx * 4 + j) : (64 + tx * 4 + j - 4);
            C[(size_t)(row0 + r) * D + col0 + c] = acc[i][j];
        }
    }
}

// Scores: for each (b, qc): WS[ti, jj] = w(jj-ti) * sum_d Q[t0+ti,d] * K[t0+jj,d]
// jj in [0, 512) indexes keys starting at t0 = qc*CHK. Guard keys beyond T.
__global__ __launch_bounds__(256) void scores_gemm(const float* __restrict__ decay_logit)
{
    const int bidx = blockIdx.y;
    const int b = bidx >> 5, qc = bidx & 31;
    const int col0 = blockIdx.x * 128;   // key-window offset tile
    const int kvalid = T - qc * CHK;     // valid keys from window base

    const float* A = g_q + (size_t)(b * T + qc * CHK) * D;
    const float* Bm = g_k + (size_t)(b * T + qc * CHK) * D;

    __shared__ float As[8][128];
    __shared__ float Bs[8][128];
    float acc[8][8];
#pragma unroll
    for (int i = 0; i < 8; i++)
#pragma unroll
        for (int j = 0; j < 8; j++) acc[i][j] = 0.f;

    const int tid = threadIdx.x;
    const int tx = tid & 15, ty = tid >> 4;
    const int ldrow = tid >> 1;
    const int ldk = (tid & 1) * 4;
    const bool brow_ok = (col0 + ldrow) < kvalid;

    for (int k0 = 0; k0 < D; k0 += 8) {
        float4 a4 = *(const float4*)(A + (size_t)ldrow * D + k0 + ldk);
        As[ldk + 0][ldrow] = a4.x; As[ldk + 1][ldrow] = a4.y;
        As[ldk + 2][ldrow] = a4.z; As[ldk + 3][ldrow] = a4.w;
        float4 b4 = make_float4(0.f, 0.f, 0.f, 0.f);
        if (brow_ok)
            b4 = *(const float4*)(Bm + (size_t)(col0 + ldrow) * D + k0 + ldk);
        Bs[ldk + 0][ldrow] = b4.x; Bs[ldk + 1][ldrow] = b4.y;
        Bs[ldk + 2][ldrow] = b4.z; Bs[ldk + 3][ldrow] = b4.w;
        __syncthreads();
#pragma unroll
        for (int kk = 0; kk < 8; kk++) {
            float ar[8], br[8];
            *(float4*)&ar[0] = *(const float4*)&As[kk][ty * 4];
            *(float4*)&ar[4] = *(const float4*)&As[kk][64 + ty * 4];
            *(float4*)&br[0] = *(const float4*)&Bs[kk][tx * 4];
            *(float4*)&br[4] = *(const float4*)&Bs[kk][64 + tx * 4];
#pragma unroll
            for (int i = 0; i < 8; i++)
#pragma unroll
                for (int j = 0; j < 8; j++) acc[i][j] += ar[i] * br[j];
        }
        __syncthreads();
    }

    const float dl = *decay_logit;
    const float decay = 1.f / (1.f + expf(-dl));
    const float l2d = log2f(decay);
    float* WS = g_ws + (size_t)(b * NQC + qc) * CHK * WKEYS;

#pragma unroll
    for (int i = 0; i < 8; i++) {
        int ti = (i < 4) ? (ty * 4 + i) : (64 + ty * 4 + i - 4);
#pragma unroll
        for (int j = 0; j < 8; j++) {
            int cj = (j < 4) ? (tx * 4 + j) : (64 + tx * 4 + j - 4);
            int jj = col0 + cj;
            int diff = jj - ti;               // s - t
            float w = (diff > 0 && jj < kvalid)
                          ? exp2f((float)(diff - 1) * l2d)
                          : 0.f;
            WS[(size_t)ti * WKEYS + jj] = acc[i][j] * w;
        }
    }
}

// Retrieved: NN GEMM per (b, qc): R[ti, dd] = sum_j WS[ti,j] * V[t0+j, dd]
__global__ __launch_bounds__(256) void retrv_gemm()
{
    const int bidx = blockIdx.y;
    const int b = bidx >> 5, qc = bidx & 31;
    const int col0 = blockIdx.x * 128;       // dd tile
    const int kvalid = T - qc * CHK;         // valid V rows (keys) from window base

    const float* A = g_ws + (size_t)(b * NQC + qc) * CHK * WKEYS;  // [128, 512]
    const float* Bm = g_v + (size_t)(b * T + qc * CHK) * D;        // [keys, D]

    __shared__ float As[8][128];
    __shared__ float Bs[8][128];
    float acc[8][8];
#pragma unroll
    for (int i = 0; i < 8; i++)
#pragma unroll
        for (int j = 0; j < 8; j++) acc[i][j] = 0.f;

    const int tid = threadIdx.x;
    const int tx = tid & 15, ty = tid >> 4;
    const int ldrow = tid >> 1;
    const int ldk = (tid & 1) * 4;
    const int bk = tid >> 5;                 // 0..7 (k row within tile)
    const int bn = (tid & 31) * 4;           // 0..124 (n offset)

    for (int k0 = 0; k0 < WKEYS; k0 += 8) {
        // A: [128 rows, K-contig] -> transpose into As[k][row]
        float4 a4 = *(const float4*)(A + (size_t)ldrow * WKEYS + k0 + ldk);
        As[ldk + 0][ldrow] = a4.x; As[ldk + 1][ldrow] = a4.y;
        As[ldk + 2][ldrow] = a4.z; As[ldk + 3][ldrow] = a4.w;
        // B: row-major [k, n]; load along n
        int krow = k0 + bk;                  // key index
        float4 b4 = make_float4(0.f, 0.f, 0.f, 0.f);
        if (krow < kvalid)
            b4 = *(const float4*)(Bm + (size_t)krow * D + col0 + bn);
        *(float4*)&Bs[bk][bn] = b4;
        __syncthreads();
#pragma unroll
        for (int kk = 0; kk < 8; kk++) {
            float ar[8], br[8];
            *(float4*)&ar[0] = *(const float4*)&As[kk][ty * 4];
            *(float4*)&ar[4] = *(const float4*)&As[kk][64 + ty * 4];
            *(float4*)&br[0] = *(const float4*)&Bs[kk][tx * 4];
            *(float4*)&br[4] = *(const float4*)&Bs[kk][64 + tx * 4];
#pragma unroll
            for (int i = 0; i < 8; i++)
#pragma unroll
                for (int j = 0; j < 8; j++) acc[i][j] += ar[i] * br[j];
        }
        __syncthreads();
    }

    float* C = g_r + (size_t)(b * T + qc * CHK) * D;
#pragma unroll
    for (int i = 0; i < 8; i++) {
        int r = (i < 4) ? (ty * 4 + i) : (64 + ty * 4 + i - 4);
#pragma unroll
        for (int j = 0; j < 8; j++) {
            int c = (j < 4) ? (tx * 4 + j) : (64 + tx * 4 + j - 4);
            C[(size_t)r * D + col0 + c] = acc[i][j];
        }
    }
}

// Output projection: out[i, jj] = out_scale * sum_d R[i,d] * Wo[jj,d]  (NT)
__global__ __launch_bounds__(256) void out_gemm(
    const float* __restrict__ Wo,
    const float* __restrict__ out_scale,
    float* __restrict__ out)
{
    const int row0 = blockIdx.y * 128;
    const int col0 = blockIdx.x * 128;

    __shared__ float As[8][128];
    __shared__ float Bs[8][128];
    float acc[8][8];
#pragma unroll
    for (int i = 0; i < 8; i++)
#pragma unroll
        for (int j = 0; j < 8; j++) acc[i][j] = 0.f;

    const int tid = threadIdx.x;
    const int tx = tid & 15, ty = tid >> 4;
    const int ldrow = tid >> 1;
    const int ldk = (tid & 1) * 4;

    const float* A = g_r + (size_t)row0 * D;
    const float* Bm = Wo + (size_t)col0 * D;

    for (int k0 = 0; k0 < D; k0 += 8) {
        float4 a4 = *(const float4*)(A + (size_t)ldrow * D + k0 + ldk);
        As[ldk + 0][ldrow] = a4.x; As[ldk + 1][ldrow] = a4.y;
        As[ldk + 2][ldrow] = a4.z; As[ldk + 3][ldrow] = a4.w;
        float4 b4 = *(const float4*)(Bm + (size_t)ldrow * D + k0 + ldk);
        Bs[ldk + 0][ldrow] = b4.x; Bs[ldk + 1][ldrow] = b4.y;
        Bs[ldk + 2][ldrow] = b4.z; Bs[ldk + 3][ldrow] = b4.w;
        __syncthreads();
#pragma unroll
        for (int kk = 0; kk < 8; kk++) {
            float ar[8], br[8];
            *(float4*)&ar[0] = *(const float4*)&As[kk][ty * 4];
            *(float4*)&ar[4] = *(const float4*)&As[kk][64 + ty * 4];
            *(float4*)&br[0] = *(const float4*)&Bs[kk][tx * 4];
            *(float4*)&br[4] = *(const float4*)&Bs[kk][64 + tx * 4];
#pragma unroll
            for (int i = 0; i < 8; i++)
#pragma unroll
                for (int j = 0; j < 8; j++) acc[i][j] += ar[i] * br[j];
        }
        __syncthreads();
    }

    const float s = *out_scale;
#pragma unroll
    for (int i = 0; i < 8; i++) {
        int r = (i < 4) ? (ty * 4 + i) : (64 + ty * 4 + i - 4);
#pragma unroll
        for (int j = 0; j < 8; j++) {
            int c = (j < 4) ? (tx * 4 + j) : (64 + tx * 4 + j - 4);
            out[(size_t)(row0 + r) * D + col0 + c] = acc[i][j] * s;
        }
    }
}

extern "C" void kernel_launch(void* const* d_in, const int* in_sizes, int n_in,
                              void* d_out, int out_size)
{
    const float* x  = (const float*)d_in[0];
    const float* Wq = (const float*)d_in[1];
    const float* Wk = (const float*)d_in[2];
    const float* Wv = (const float*)d_in[3];
    const float* Wo = (const float*)d_in[4];
    const float* dl = (const float*)d_in[5];
    const float* os = (const float*)d_in[6];
    float* out = (float*)d_out;

    dim3 blk(256);
    qkv_gemm<<<dim3(4, MTOT / 128, 3), blk>>>(x, Wq, Wk, Wv);
    scores_gemm<<<dim3(4, BATCH * NQC), blk>>>(dl);
    retrv_gemm<<<dim3(4, BATCH * NQC), blk>>>();
    out_gemm<<<dim3(4, MTOT / 128), blk>>>(Wo, os, out);
}

// round 2
// speedup vs baseline: 2.4314x; 2.4314x over previous
#include <cuda_runtime.h>
#include <math.h>

// Problem constants
#define BATCH 4
#define T 4096
#define D 512
#define CHK 128
#define NQC 32                  // T / CHK
#define WKEYS 512               // banded window: decay^383 ~ 8e-9, negligible tail
#define MTOT 16384              // BATCH * T

// Scratch
__device__ float g_q[BATCH * T * D];
__device__ float g_k[BATCH * T * D];
__device__ float g_v[BATCH * T * D];
__device__ float g_ws[BATCH * NQC * CHK * WKEYS];
__device__ float g_r[BATCH * T * D];

// ---------------------------------------------------------------------------
// tf32 helpers
// ---------------------------------------------------------------------------
__device__ __forceinline__ float to_tf32(float x) {
    float r;
    asm("cvt.rna.tf32.f32 %0, %1;" : "=f"(r) : "f"(x));
    return r;
}

__device__ __forceinline__ void mma8(float* c, const float* a, const float* b) {
    asm volatile(
        "mma.sync.aligned.m16n8k8.row.col.f32.tf32.tf32.f32 "
        "{%0,%1,%2,%3}, {%4,%5,%6,%7}, {%8,%9}, {%0,%1,%2,%3};\n"
        : "+f"(c[0]), "+f"(c[1]), "+f"(c[2]), "+f"(c[3])
        : "r"(__float_as_uint(a[0])), "r"(__float_as_uint(a[1])),
          "r"(__float_as_uint(a[2])), "r"(__float_as_uint(a[3])),
          "r"(__float_as_uint(b[0])), "r"(__float_as_uint(b[1])));
}

// ---------------------------------------------------------------------------
// Tile config: CTA 128x128, 4 warps (2x2), warp tile 64x64, BK=16.
// Smem A/B stored [row][k] with pitch 20 -> fragment LDS conflict-free.
// ---------------------------------------------------------------------------
#define PK 20

// Load a 128x16 K-contiguous tile (row-major, leading dim ld) into S[128][20],
// rounding to tf32. Rows >= rowlim are zero-filled.
__device__ __forceinline__ void load_kc_tile(
    float (*S)[PK], const float* src, int ld, int k0, int tid, int rowlim)
{
    const int r0 = tid >> 2;
    const int koff = (tid & 3) * 4;
#pragma unroll
    for (int it = 0; it < 4; it++) {
        int r = r0 + it * 32;
        float4 v = make_float4(0.f, 0.f, 0.f, 0.f);
        if (r < rowlim)
            v = *(const float4*)(src + (size_t)r * ld + k0 + koff);
        float4 w = make_float4(to_tf32(v.x), to_tf32(v.y), to_tf32(v.z), to_tf32(v.w));
        *(float4*)&S[r][koff] = w;
    }
}

// MMA over one 16-deep smem tile; A and B both [row][k] pitch-20 (NT form).
__device__ __forceinline__ void mma_tile_nt(
    const float (*As)[PK], const float (*Bs)[PK],
    float acc[4][8][4], int wm, int wn, int g, int c)
{
#pragma unroll
    for (int kb = 0; kb < 16; kb += 8) {
        float a[4][4];
#pragma unroll
        for (int mi = 0; mi < 4; mi++) {
            const float* Ar0 = &As[wm + mi * 16 + g][kb + c];
            const float* Ar8 = &As[wm + mi * 16 + g + 8][kb + c];
            a[mi][0] = Ar0[0];
            a[mi][1] = Ar8[0];
            a[mi][2] = Ar0[4];
            a[mi][3] = Ar8[4];
        }
#pragma unroll
        for (int ni = 0; ni < 8; ni++) {
            float b[2];
            const float* Br = &Bs[wn + ni * 8 + g][kb + c];
            b[0] = Br[0];
            b[1] = Br[4];
#pragma unroll
            for (int mi = 0; mi < 4; mi++)
                mma8(acc[mi][ni], a[mi], b);
        }
    }
}

// ---------------------------------------------------------------------------
// Kernel 1: QKV projections  C = x @ W^T   (M=16384, N=512, K=512) x3
// ---------------------------------------------------------------------------
__global__ __launch_bounds__(128) void qkv_gemm(
    const float* __restrict__ x,
    const float* __restrict__ Wq,
    const float* __restrict__ Wk,
    const float* __restrict__ Wv)
{
    const float* W = (blockIdx.z == 0) ? Wq : (blockIdx.z == 1) ? Wk : Wv;
    float* C = (blockIdx.z == 0) ? g_q : (blockIdx.z == 1) ? g_k : g_v;

    const int row0 = blockIdx.y * 128;
    const int col0 = blockIdx.x * 128;

    __shared__ float As[128][PK];
    __shared__ float Bs[128][PK];

    float acc[4][8][4];
#pragma unroll
    for (int i = 0; i < 4; i++)
#pragma unroll
        for (int j = 0; j < 8; j++)
#pragma unroll
            for (int q = 0; q < 4; q++) acc[i][j][q] = 0.f;

    const int tid = threadIdx.x;
    const int warp = tid >> 5, lane = tid & 31;
    const int wm = (warp >> 1) * 64, wn = (warp & 1) * 64;
    const int g = lane >> 2, c = lane & 3;

    const float* A = x + (size_t)row0 * D;
    const float* B = W + (size_t)col0 * D;

    for (int k0 = 0; k0 < D; k0 += 16) {
        load_kc_tile(As, A, D, k0, tid, 128);
        load_kc_tile(Bs, B, D, k0, tid, 128);
        __syncthreads();
        mma_tile_nt(As, Bs, acc, wm, wn, g, c);
        __syncthreads();
    }

    float* Cp = C + (size_t)row0 * D + col0;
#pragma unroll
    for (int mi = 0; mi < 4; mi++)
#pragma unroll
        for (int ni = 0; ni < 8; ni++) {
            int row = wm + mi * 16 + g;
            int col = wn + ni * 8 + 2 * c;
            *(float2*)&Cp[(size_t)row * D + col] =
                make_float2(acc[mi][ni][0], acc[mi][ni][1]);
            *(float2*)&Cp[(size_t)(row + 8) * D + col] =
                make_float2(acc[mi][ni][2], acc[mi][ni][3]);
        }
}

// ---------------------------------------------------------------------------
// Kernel 2: banded scores + decay weight epilogue.
// Per (b,qc): WS[ti,jj] = w(jj-ti) * sum_d Q[t0+ti,d]*K[t0+jj,d], jj in [0,512)
// ---------------------------------------------------------------------------
__global__ __launch_bounds__(128) void scores_gemm(const float* __restrict__ decay_logit)
{
    const int bidx = blockIdx.y;
    const int b = bidx >> 5, qc = bidx & 31;
    const int col0 = blockIdx.x * 128;
    const int kvalid = T - qc * CHK;

    const float* A = g_q + (size_t)(b * T + qc * CHK) * D;
    const float* B = g_k + (size_t)(b * T + qc * CHK + col0) * D;
    const int blim = min(128, max(0, kvalid - col0));

    __shared__ float As[128][PK];
    __shared__ float Bs[128][PK];

    float acc[4][8][4];
#pragma unroll
    for (int i = 0; i < 4; i++)
#pragma unroll
        for (int j = 0; j < 8; j++)
#pragma unroll
            for (int q = 0; q < 4; q++) acc[i][j][q] = 0.f;

    const int tid = threadIdx.x;
    const int warp = tid >> 5, lane = tid & 31;
    const int wm = (warp >> 1) * 64, wn = (warp & 1) * 64;
    const int g = lane >> 2, c = lane & 3;

    for (int k0 = 0; k0 < D; k0 += 16) {
        load_kc_tile(As, A, D, k0, tid, 128);
        load_kc_tile(Bs, B, D, k0, tid, blim);
        __syncthreads();
        mma_tile_nt(As, Bs, acc, wm, wn, g, c);
        __syncthreads();
    }

    const float dl = *decay_logit;
    const float decay = 1.f / (1.f + expf(-dl));
    const float l2d = log2f(decay);
    float* WS = g_ws + (size_t)(b * NQC + qc) * CHK * WKEYS;

#pragma unroll
    for (int mi = 0; mi < 4; mi++)
#pragma unroll
        for (int ni = 0; ni < 8; ni++) {
#pragma unroll
            for (int half = 0; half < 2; half++) {
                int ti = wm + mi * 16 + g + half * 8;
                float2 o;
#pragma unroll
                for (int e = 0; e < 2; e++) {
                    int jj = col0 + wn + ni * 8 + 2 * c + e;
                    int diff = jj - ti;
                    float w = (diff > 0 && jj < kvalid)
                                  ? exp2f((float)(diff - 1) * l2d)
                                  : 0.f;
                    float v = acc[mi][ni][half * 2 + e] * w;
                    if (e == 0) o.x = v; else o.y = v;
                }
                int jj0 = col0 + wn + ni * 8 + 2 * c;
                *(float2*)&WS[(size_t)ti * WKEYS + jj0] = o;
            }
        }
}

// ---------------------------------------------------------------------------
// Kernel 3: retrieved = WS @ V_window  (NN). Per (b,qc): [128,512]@[512,512]
// ---------------------------------------------------------------------------
#define PN 132
__device__ __forceinline__ void load_nc_tile(
    float (*S)[PN], const float* src, int ld, int k0, int tid, int rowlim)
{
    const int c4 = (tid & 31) * 4;
    const int r0 = tid >> 5;
#pragma unroll
    for (int it = 0; it < 4; it++) {
        int r = r0 + it * 4;      // 0..15 (k within tile)
        float4 v = make_float4(0.f, 0.f, 0.f, 0.f);
        if (k0 + r < rowlim)
            v = *(const float4*)(src + (size_t)(k0 + r) * ld + c4);
        float4 w = make_float4(to_tf32(v.x), to_tf32(v.y), to_tf32(v.z), to_tf32(v.w));
        *(float4*)&S[r][c4] = w;
    }
}

__global__ __launch_bounds__(128) void retrv_gemm()
{
    const int bidx = blockIdx.y;
    const int b = bidx >> 5, qc = bidx & 31;
    const int col0 = blockIdx.x * 128;
    const int kvalid = T - qc * CHK;

    const float* A = g_ws + (size_t)(b * NQC + qc) * CHK * WKEYS;
    const float* B = g_v + (size_t)(b * T + qc * CHK) * D + col0;

    __shared__ float As[128][PK];
    __shared__ float Bs[16][PN];

    float acc[4][8][4];
#pragma unroll
    for (int i = 0; i < 4; i++)
#pragma unroll
        for (int j = 0; j < 8; j++)
#pragma unroll
            for (int q = 0; q < 4; q++) acc[i][j][q] = 0.f;

    const int tid = threadIdx.x;
    const int warp = tid >> 5, lane = tid & 31;
    const int wm = (warp >> 1) * 64, wn = (warp & 1) * 64;
    const int g = lane >> 2, c = lane & 3;

    for (int k0 = 0; k0 < WKEYS; k0 += 16) {
        load_kc_tile(As, A, WKEYS, k0, tid, 128);
        load_nc_tile(Bs, B, D, k0, tid, kvalid);
        __syncthreads();
#pragma unroll
        for (int kb = 0; kb < 16; kb += 8) {
            float a[4][4];
#pragma unroll
            for (int mi = 0; mi < 4; mi++) {
                const float* Ar0 = &As[wm + mi * 16 + g][kb + c];
                const float* Ar8 = &As[wm + mi * 16 + g + 8][kb + c];
                a[mi][0] = Ar0[0];
                a[mi][1] = Ar8[0];
                a[mi][2] = Ar0[4];
                a[mi][3] = Ar8[4];
            }
#pragma unroll
            for (int ni = 0; ni < 8; ni++) {
                float bfr[2];
                bfr[0] = Bs[kb + c][wn + ni * 8 + g];
                bfr[1] = Bs[kb + c + 4][wn + ni * 8 + g];
#pragma unroll
                for (int mi = 0; mi < 4; mi++)
                    mma8(acc[mi][ni], a[mi], bfr);
            }
        }
        __syncthreads();
    }

    float* C = g_r + (size_t)(b * T + qc * CHK) * D + col0;
#pragma unroll
    for (int mi = 0; mi < 4; mi++)
#pragma unroll
        for (int ni = 0; ni < 8; ni++) {
            int row = wm + mi * 16 + g;
            int col = wn + ni * 8 + 2 * c;
            *(float2*)&C[(size_t)row * D + col] =
                make_float2(acc[mi][ni][0], acc[mi][ni][1]);
            *(float2*)&C[(size_t)(row + 8) * D + col] =
                make_float2(acc[mi][ni][2], acc[mi][ni][3]);
        }
}

// ---------------------------------------------------------------------------
// Kernel 4: out = (R @ Wo^T) * out_scale   (NT)
// ---------------------------------------------------------------------------
__global__ __launch_bounds__(128) void out_gemm(
    const float* __restrict__ Wo,
    const float* __restrict__ out_scale,
    float* __restrict__ out)
{
    const int row0 = blockIdx.y * 128;
    const int col0 = blockIdx.x * 128;

    __shared__ float As[128][PK];
    __shared__ float Bs[128][PK];

    float acc[4][8][4];
#pragma unroll
    for (int i = 0; i < 4; i++)
#pragma unroll
        for (int j = 0; j < 8; j++)
#pragma unroll
            for (int q = 0; q < 4; q++) acc[i][j][q] = 0.f;

    const int tid = threadIdx.x;
    const int warp = tid >> 5, lane = tid & 31;
    const int wm = (warp >> 1) * 64, wn = (warp & 1) * 64;
    const int g = lane >> 2, c = lane & 3;

    const float* A = g_r + (size_t)row0 * D;
    const float* B = Wo + (size_t)col0 * D;

    for (int k0 = 0; k0 < D; k0 += 16) {
        load_kc_tile(As, A, D, k0, tid, 128);
        load_kc_tile(Bs, B, D, k0, tid, 128);
        __syncthreads();
        mma_tile_nt(As, Bs, acc, wm, wn, g, c);
        __syncthreads();
    }

    const float s = *out_scale;
    float* Cp = out + (size_t)row0 * D + col0;
#pragma unroll
    for (int mi = 0; mi < 4; mi++)
#pragma unroll
        for (int ni = 0; ni < 8; ni++) {
            int row = wm + mi * 16 + g;
            int col = wn + ni * 8 + 2 * c;
            *(float2*)&Cp[(size_t)row * D + col] =
                make_float2(acc[mi][ni][0] * s, acc[mi][ni][1] * s);
            *(float2*)&Cp[(size_t)(row + 8) * D + col] =
                make_float2(acc[mi][ni][2] * s, acc[mi][ni][3] * s);
        }
}

extern "C" void kernel_launch(void* const* d_in, const int* in_sizes, int n_in,
                              void* d_out, int out_size)
{
    const float* x  = (const float*)d_in[0];
    const float* Wq = (const float*)d_in[1];
    const float* Wk = (const float*)d_in[2];
    const float* Wv = (const float*)d_in[3];
    const float* Wo = (const float*)d_in[4];
    const float* dl = (const float*)d_in[5];
    const float* os = (const float*)d_in[6];
    float* out = (float*)d_out;

    dim3 blk(128);
    qkv_gemm<<<dim3(4, MTOT / 128, 3), blk>>>(x, Wq, Wk, Wv);
    scores_gemm<<<dim3(4, BATCH * NQC), blk>>>(dl);
    retrv_gemm<<<dim3(4, BATCH * NQC), blk>>>();
    out_gemm<<<dim3(4, MTOT / 128), blk>>>(Wo, os, out);
}

// round 3
// speedup vs baseline: 3.0815x; 1.2674x over previous
#include <cuda_runtime.h>
#include <math.h>

// Problem constants
#define BATCH 4
#define T 4096
#define D 512
#define CHK 128
#define NQC 32                  // T / CHK
#define WKEYS 512               // banded window: decay^383 ~ 8e-9, negligible tail
#define MTOT 16384              // BATCH * T

// Scratch
__device__ float g_q[BATCH * T * D];
__device__ float g_k[BATCH * T * D];
__device__ float g_v[BATCH * T * D];
__device__ float g_ws[BATCH * NQC * CHK * WKEYS];
__device__ float g_r[BATCH * T * D];

// ---------------------------------------------------------------------------
// tf32 helpers
// ---------------------------------------------------------------------------
__device__ __forceinline__ float to_tf32(float x) {
    float r;
    asm("cvt.rna.tf32.f32 %0, %1;" : "=f"(r) : "f"(x));
    return r;
}

__device__ __forceinline__ void mma8(float* c, const float* a, const float* b) {
    asm volatile(
        "mma.sync.aligned.m16n8k8.row.col.f32.tf32.tf32.f32 "
        "{%0,%1,%2,%3}, {%4,%5,%6,%7}, {%8,%9}, {%0,%1,%2,%3};\n"
        : "+f"(c[0]), "+f"(c[1]), "+f"(c[2]), "+f"(c[3])
        : "r"(__float_as_uint(a[0])), "r"(__float_as_uint(a[1])),
          "r"(__float_as_uint(a[2])), "r"(__float_as_uint(a[3])),
          "r"(__float_as_uint(b[0])), "r"(__float_as_uint(b[1])));
}

// ---------------------------------------------------------------------------
// Tile config: CTA 128x128, 4 warps (2x2), warp tile 64x64, BK=16.
// 2-stage double-buffered smem; global prefetch into registers.
// Smem [row][k] pitch 20 -> conflict-free fragment LDS.
// ---------------------------------------------------------------------------
#define PK 20

// LDG a 128x16 K-contiguous tile into 4 x float4 regs (zero-fill past rowlim).
__device__ __forceinline__ void ldg_kc(
    float4* p, const float* src, int ld, int k0, int tid, int rowlim)
{
    const int r0 = tid >> 2;
    const int koff = (tid & 3) * 4;
#pragma unroll
    for (int it = 0; it < 4; it++) {
        int r = r0 + it * 32;
        p[it] = make_float4(0.f, 0.f, 0.f, 0.f);
        if (r < rowlim)
            p[it] = *(const float4*)(src + (size_t)r * ld + k0 + koff);
    }
}

// STS regs -> stage with tf32 rounding.
__device__ __forceinline__ void sts_kc(float (*S)[PK], const float4* p, int tid)
{
    const int r0 = tid >> 2;
    const int koff = (tid & 3) * 4;
#pragma unroll
    for (int it = 0; it < 4; it++) {
        int r = r0 + it * 32;
        *(float4*)&S[r][koff] = make_float4(
            to_tf32(p[it].x), to_tf32(p[it].y), to_tf32(p[it].z), to_tf32(p[it].w));
    }
}

// MMA over one 16-deep smem stage; A and B both [row][k] pitch-20 (NT form).
__device__ __forceinline__ void mma_tile_nt(
    const float (*As)[PK], const float (*Bs)[PK],
    float acc[4][8][4], int wm, int wn, int g, int c)
{
#pragma unroll
    for (int kb = 0; kb < 16; kb += 8) {
        float a[4][4];
#pragma unroll
        for (int mi = 0; mi < 4; mi++) {
            const float* Ar0 = &As[wm + mi * 16 + g][kb + c];
            const float* Ar8 = &As[wm + mi * 16 + g + 8][kb + c];
            a[mi][0] = Ar0[0];
            a[mi][1] = Ar8[0];
            a[mi][2] = Ar0[4];
            a[mi][3] = Ar8[4];
        }
#pragma unroll
        for (int ni = 0; ni < 8; ni++) {
            float b[2];
            const float* Br = &Bs[wn + ni * 8 + g][kb + c];
            b[0] = Br[0];
            b[1] = Br[4];
#pragma unroll
            for (int mi = 0; mi < 4; mi++)
                mma8(acc[mi][ni], a[mi], b);
        }
    }
}

#define ACC_INIT(acc)                                   \
    _Pragma("unroll")                                   \
    for (int i = 0; i < 4; i++)                         \
        _Pragma("unroll")                               \
        for (int j = 0; j < 8; j++)                     \
            _Pragma("unroll")                           \
            for (int q = 0; q < 4; q++) acc[i][j][q] = 0.f;

// ---------------------------------------------------------------------------
// Kernel 1: QKV projections  C = x @ W^T   (M=16384, N=512, K=512) x3
// ---------------------------------------------------------------------------
__global__ __launch_bounds__(128, 2) void qkv_gemm(
    const float* __restrict__ x,
    const float* __restrict__ Wq,
    const float* __restrict__ Wk,
    const float* __restrict__ Wv)
{
    const float* W = (blockIdx.z == 0) ? Wq : (blockIdx.z == 1) ? Wk : Wv;
    float* C = (blockIdx.z == 0) ? g_q : (blockIdx.z == 1) ? g_k : g_v;

    const int row0 = blockIdx.y * 128;
    const int col0 = blockIdx.x * 128;

    __shared__ float As[2][128][PK];
    __shared__ float Bs[2][128][PK];

    float acc[4][8][4];
    ACC_INIT(acc);

    const int tid = threadIdx.x;
    const int warp = tid >> 5, lane = tid & 31;
    const int wm = (warp >> 1) * 64, wn = (warp & 1) * 64;
    const int g = lane >> 2, c = lane & 3;

    const float* A = x + (size_t)row0 * D;
    const float* B = W + (size_t)col0 * D;

    float4 pa[4], pb[4];
    ldg_kc(pa, A, D, 0, tid, 128);
    ldg_kc(pb, B, D, 0, tid, 128);
    int s = 0;
    sts_kc(As[0], pa, tid);
    sts_kc(Bs[0], pb, tid);
    __syncthreads();

    for (int k0 = 16; k0 <= D; k0 += 16) {
        if (k0 < D) {
            ldg_kc(pa, A, D, k0, tid, 128);
            ldg_kc(pb, B, D, k0, tid, 128);
        }
        mma_tile_nt(As[s], Bs[s], acc, wm, wn, g, c);
        if (k0 < D) {
            sts_kc(As[s ^ 1], pa, tid);
            sts_kc(Bs[s ^ 1], pb, tid);
        }
        __syncthreads();
        s ^= 1;
    }

    float* Cp = C + (size_t)row0 * D + col0;
#pragma unroll
    for (int mi = 0; mi < 4; mi++)
#pragma unroll
        for (int ni = 0; ni < 8; ni++) {
            int row = wm + mi * 16 + g;
            int col = wn + ni * 8 + 2 * c;
            *(float2*)&Cp[(size_t)row * D + col] =
                make_float2(acc[mi][ni][0], acc[mi][ni][1]);
            *(float2*)&Cp[(size_t)(row + 8) * D + col] =
                make_float2(acc[mi][ni][2], acc[mi][ni][3]);
        }
}

// ---------------------------------------------------------------------------
// Kernel 2: banded scores + decay weight epilogue.
// ---------------------------------------------------------------------------
__global__ __launch_bounds__(128, 2) void scores_gemm(const float* __restrict__ decay_logit)
{
    const int bidx = blockIdx.y;
    const int b = bidx >> 5, qc = bidx & 31;
    const int col0 = blockIdx.x * 128;
    const int kvalid = T - qc * CHK;

    const float* A = g_q + (size_t)(b * T + qc * CHK) * D;
    const float* B = g_k + (size_t)(b * T + qc * CHK + col0) * D;
    const int blim = min(128, max(0, kvalid - col0));

    __shared__ float As[2][128][PK];
    __shared__ float Bs[2][128][PK];

    float acc[4][8][4];
    ACC_INIT(acc);

    const int tid = threadIdx.x;
    const int warp = tid >> 5, lane = tid & 31;
    const int wm = (warp >> 1) * 64, wn = (warp & 1) * 64;
    const int g = lane >> 2, c = lane & 3;

    float4 pa[4], pb[4];
    ldg_kc(pa, A, D, 0, tid, 128);
    ldg_kc(pb, B, D, 0, tid, blim);
    int s = 0;
    sts_kc(As[0], pa, tid);
    sts_kc(Bs[0], pb, tid);
    __syncthreads();

    for (int k0 = 16; k0 <= D; k0 += 16) {
        if (k0 < D) {
            ldg_kc(pa, A, D, k0, tid, 128);
            ldg_kc(pb, B, D, k0, tid, blim);
        }
        mma_tile_nt(As[s], Bs[s], acc, wm, wn, g, c);
        if (k0 < D) {
            sts_kc(As[s ^ 1], pa, tid);
            sts_kc(Bs[s ^ 1], pb, tid);
        }
        __syncthreads();
        s ^= 1;
    }

    const float dl = *decay_logit;
    const float decay = 1.f / (1.f + expf(-dl));
    const float l2d = log2f(decay);
    float* WS = g_ws + (size_t)(b * NQC + qc) * CHK * WKEYS;

#pragma unroll
    for (int mi = 0; mi < 4; mi++)
#pragma unroll
        for (int ni = 0; ni < 8; ni++) {
#pragma unroll
            for (int half = 0; half < 2; half++) {
                int ti = wm + mi * 16 + g + half * 8;
                float2 o;
#pragma unroll
                for (int e = 0; e < 2; e++) {
                    int jj = col0 + wn + ni * 8 + 2 * c + e;
                    int diff = jj - ti;
                    float w = (diff > 0 && jj < kvalid)
                                  ? exp2f((float)(diff - 1) * l2d)
                                  : 0.f;
                    float v = acc[mi][ni][half * 2 + e] * w;
                    if (e == 0) o.x = v; else o.y = v;
                }
                int jj0 = col0 + wn + ni * 8 + 2 * c;
                *(float2*)&WS[(size_t)ti * WKEYS + jj0] = o;
            }
        }
}

// ---------------------------------------------------------------------------
// Kernel 3: retrieved = WS @ V_window  (NN). Per (b,qc): [128,512]@[512,512]
// ---------------------------------------------------------------------------
#define PN 132

__device__ __forceinline__ void ldg_nc(
    float4* p, const float* src, int ld, int k0, int tid, int rowlim)
{
    const int c4 = (tid & 31) * 4;
    const int r0 = tid >> 5;
#pragma unroll
    for (int it = 0; it < 4; it++) {
        int r = r0 + it * 4;
        p[it] = make_float4(0.f, 0.f, 0.f, 0.f);
        if (k0 + r < rowlim)
            p[it] = *(const float4*)(src + (size_t)(k0 + r) * ld + c4);
    }
}

__device__ __forceinline__ void sts_nc(float (*S)[PN], const float4* p, int tid)
{
    const int c4 = (tid & 31) * 4;
    const int r0 = tid >> 5;
#pragma unroll
    for (int it = 0; it < 4; it++) {
        int r = r0 + it * 4;
        *(float4*)&S[r][c4] = make_float4(
            to_tf32(p[it].x), to_tf32(p[it].y), to_tf32(p[it].z), to_tf32(p[it].w));
    }
}

__global__ __launch_bounds__(128, 2) void retrv_gemm()
{
    const int bidx = blockIdx.y;
    const int b = bidx >> 5, qc = bidx & 31;
    const int col0 = blockIdx.x * 128;
    const int kvalid = T - qc * CHK;

    const float* A = g_ws + (size_t)(b * NQC + qc) * CHK * WKEYS;
    const float* B = g_v + (size_t)(b * T + qc * CHK) * D + col0;

    __shared__ float As[2][128][PK];
    __shared__ float Bs[2][16][PN];

    float acc[4][8][4];
    ACC_INIT(acc);

    const int tid = threadIdx.x;
    const int warp = tid >> 5, lane = tid & 31;
    const int wm = (warp >> 1) * 64, wn = (warp & 1) * 64;
    const int g = lane >> 2, c = lane & 3;

    float4 pa[4], pb[4];
    ldg_kc(pa, A, WKEYS, 0, tid, 128);
    ldg_nc(pb, B, D, 0, tid, kvalid);
    int s = 0;
    sts_kc(As[0], pa, tid);
    sts_nc(Bs[0], pb, tid);
    __syncthreads();

    for (int k0 = 16; k0 <= WKEYS; k0 += 16) {
        if (k0 < WKEYS) {
            ldg_kc(pa, A, WKEYS, k0, tid, 128);
            ldg_nc(pb, B, D, k0, tid, kvalid);
        }
#pragma unroll
        for (int kb = 0; kb < 16; kb += 8) {
            float a[4][4];
#pragma unroll
            for (int mi = 0; mi < 4; mi++) {
                const float* Ar0 = &As[s][wm + mi * 16 + g][kb + c];
                const float* Ar8 = &As[s][wm + mi * 16 + g + 8][kb + c];
                a[mi][0] = Ar0[0];
                a[mi][1] = Ar8[0];
                a[mi][2] = Ar0[4];
                a[mi][3] = Ar8[4];
            }
#pragma unroll
            for (int ni = 0; ni < 8; ni++) {
                float bfr[2];
                bfr[0] = Bs[s][kb + c][wn + ni * 8 + g];
                bfr[1] = Bs[s][kb + c + 4][wn + ni * 8 + g];
#pragma unroll
                for (int mi = 0; mi < 4; mi++)
                    mma8(acc[mi][ni], a[mi], bfr);
            }
        }
        if (k0 < WKEYS) {
            sts_kc(As[s ^ 1], pa, tid);
            sts_nc(Bs[s ^ 1], pb, tid);
        }
        __syncthreads();
        s ^= 1;
    }

    float* C = g_r + (size_t)(b * T + qc * CHK) * D + col0;
#pragma unroll
    for (int mi = 0; mi < 4; mi++)
#pragma unroll
        for (int ni = 0; ni < 8; ni++) {
            int row = wm + mi * 16 + g;
            int col = wn + ni * 8 + 2 * c;
            *(float2*)&C[(size_t)row * D + col] =
                make_float2(acc[mi][ni][0], acc[mi][ni][1]);
            *(float2*)&C[(size_t)(row + 8) * D + col] =
                make_float2(acc[mi][ni][2], acc[mi][ni][3]);
        }
}

// ---------------------------------------------------------------------------
// Kernel 4: out = (R @ Wo^T) * out_scale   (NT)
// ---------------------------------------------------------------------------
__global__ __launch_bounds__(128, 2) void out_gemm(
    const float* __restrict__ Wo,
    const float* __restrict__ out_scale,
    float* __restrict__ out)
{
    const int row0 = blockIdx.y * 128;
    const int col0 = blockIdx.x * 128;

    __shared__ float As[2][128][PK];
    __shared__ float Bs[2][128][PK];

    float acc[4][8][4];
    ACC_INIT(acc);

    const int tid = threadIdx.x;
    const int warp = tid >> 5, lane = tid & 31;
    const int wm = (warp >> 1) * 64, wn = (warp & 1) * 64;
    const int g = lane >> 2, c = lane & 3;

    const float* A = g_r + (size_t)row0 * D;
    const float* B = Wo + (size_t)col0 * D;

    float4 pa[4], pb[4];
    ldg_kc(pa, A, D, 0, tid, 128);
    ldg_kc(pb, B, D, 0, tid, 128);
    int s = 0;
    sts_kc(As[0], pa, tid);
    sts_kc(Bs[0], pb, tid);
    __syncthreads();

    for (int k0 = 16; k0 <= D; k0 += 16) {
        if (k0 < D) {
            ldg_kc(pa, A, D, k0, tid, 128);
            ldg_kc(pb, B, D, k0, tid, 128);
        }
        mma_tile_nt(As[s], Bs[s], acc, wm, wn, g, c);
        if (k0 < D) {
            sts_kc(As[s ^ 1], pa, tid);
            sts_kc(Bs[s ^ 1], pb, tid);
        }
        __syncthreads();
        s ^= 1;
    }

    const float sc = *out_scale;
    float* Cp = out + (size_t)row0 * D + col0;
#pragma unroll
    for (int mi = 0; mi < 4; mi++)
#pragma unroll
        for (int ni = 0; ni < 8; ni++) {
            int row = wm + mi * 16 + g;
            int col = wn + ni * 8 + 2 * c;
            *(float2*)&Cp[(size_t)row * D + col] =
                make_float2(acc[mi][ni][0] * sc, acc[mi][ni][1] * sc);
            *(float2*)&Cp[(size_t)(row + 8) * D + col] =
                make_float2(acc[mi][ni][2] * sc, acc[mi][ni][3] * sc);
        }
}

extern "C" void kernel_launch(void* const* d_in, const int* in_sizes, int n_in,
                              void* d_out, int out_size)
{
    const float* x  = (const float*)d_in[0];
    const float* Wq = (const float*)d_in[1];
    const float* Wk = (const float*)d_in[2];
    const float* Wv = (const float*)d_in[3];
    const float* Wo = (const float*)d_in[4];
    const float* dl = (const float*)d_in[5];
    const float* os = (const float*)d_in[6];
    float* out = (float*)d_out;

    dim3 blk(128);
    qkv_gemm<<<dim3(4, MTOT / 128, 3), blk>>>(x, Wq, Wk, Wv);
    scores_gemm<<<dim3(4, BATCH * NQC), blk>>>(dl);
    retrv_gemm<<<dim3(4, BATCH * NQC), blk>>>();
    out_gemm<<<dim3(4, MTOT / 128), blk>>>(Wo, os, out);
}